// round 10
// baseline (speedup 1.0000x reference)
#include <cuda_runtime.h>
#include <cuda_fp16.h>

#define NB 2
#define HH 512
#define WW 512
#define MASK 511
#define HW (HH*WW)

#define LANES 32        // threads per row = full warp; thread owns cols (c, c+32)
#define TYv 8
#define RPT 2
#define TILE_W 64
#define TILE_H 16       // TYv * RPT
#define NTHR (LANES*TYv)   // 256

#define RC_ROWS 20      // template rows -2..17
#define YP_ROWS 30      // y rows -7..22
#define YP_COLS 46      // y col (.x): -7..38 ; (.y) = +32
#define BP_ROWS 26      // B/x rows -5..20
#define BP_COLS 42      // col (.x): -5..36 ; (.y) = +32

#define RC_STRIDE (11*LANES)   // 352

// offsets in u64 units
#define OFF_RC 0
#define OFF_YP (RC_ROWS*RC_STRIDE)             // 7040
#define OFF_BP (OFF_YP + YP_ROWS*YP_COLS)      // 8420
#define OFF_XH (OFF_BP + BP_ROWS*BP_COLS)      // 9512
#define XH_PLANE (BP_ROWS*BP_COLS)             // 1092 u32 per channel
#define SMEM_U64 (OFF_XH + (3*XH_PLANE + 1)/2) // 9512 + 1638 = 11150
#define SMEM_BYTES (SMEM_U64*8)                // 89200

typedef unsigned long long u64;

__device__ __forceinline__ float lo_(u64 v){ return __uint_as_float((unsigned)v); }
__device__ __forceinline__ float hi_(u64 v){ return __uint_as_float((unsigned)(v >> 32)); }
__device__ __forceinline__ u64 pk_(float a, float b){ u64 r; asm("mov.b64 %0, {%1, %2};" : "=l"(r) : "f"(a), "f"(b)); return r; }
__device__ __forceinline__ u64 fma2_(u64 a, u64 b, u64 c){ u64 d; asm("fma.rn.f32x2 %0, %1, %2, %3;" : "=l"(d) : "l"(a), "l"(b), "l"(c)); return d; }
__device__ __forceinline__ u64 add2_(u64 a, u64 b){ u64 d; asm("add.rn.f32x2 %0, %1, %2;" : "=l"(d) : "l"(a), "l"(b)); return d; }
__device__ __forceinline__ u64 mul2_(u64 a, u64 b){ u64 d; asm("mul.rn.f32x2 %0, %1, %2;" : "=l"(d) : "l"(a), "l"(b)); return d; }
__device__ __forceinline__ float fsqrt_a(float x){ float y; asm("sqrt.approx.f32 %0, %1;" : "=f"(y) : "f"(x)); return y; }
__device__ __forceinline__ float fex2_a (float x){ float y; asm("ex2.approx.f32 %0, %1;"  : "=f"(y) : "f"(x)); return y; }
__device__ __forceinline__ float frcp_a (float x){ float y; asm("rcp.approx.f32 %0, %1;"  : "=f"(y) : "f"(x)); return y; }

#define NEG2_2 0xC0000000C0000000ULL   // {-2.f, -2.f}
#define NEG1_2 0xBF800000BF800000ULL   // {-1.f, -1.f}

__global__ void __launch_bounds__(NTHR, 2) nlm_kernel(const float* __restrict__ x,
                                                      float* __restrict__ out){
    extern __shared__ u64 smem[];
    u64* rcS = smem + OFF_RC;     // [rr][s][lane]
    u64* sYp = smem + OFF_YP;     // [r][jj] packed clipped luminance
    u64* sBp = smem + OFF_BP;     // [rb][jj] box5x5(y^2)
    unsigned* xh = (unsigned*)(smem + OFF_XH);  // [ch][rb][jj] half2 x
    u64* sHp = smem + OFF_RC;     // alias: transient hbox(y^2), [r][jj] 30x42

    const int n   = blockIdx.z;
    const int c0  = blockIdx.x * TILE_W;
    const int r0  = blockIdx.y * TILE_H;
    const int tid = threadIdx.y * LANES + threadIdx.x;
    const float* xb = x + (size_t)n*3*HW;

    // ---- sYp: packed clipped luminance, pair {col, col+32} ----
    for (int i = tid; i < YP_ROWS*YP_COLS; i += NTHR){
        int r = i / YP_COLS, jj = i - r*YP_COLS;
        int base = ((r0 + r - 7) & MASK) << 9;
        int gx = base | ((c0 + jj - 7) & MASK);
        int gy = base | ((c0 + jj + 25) & MASK);
        float l0 = 0.299f*__saturatef(xb[gx]) + 0.587f*__saturatef(xb[HW+gx]) + 0.114f*__saturatef(xb[2*HW+gx]);
        float l1 = 0.299f*__saturatef(xb[gy]) + 0.587f*__saturatef(xb[HW+gy]) + 0.114f*__saturatef(xb[2*HW+gy]);
        sYp[i] = pk_(l0, l1);
    }
    __syncthreads();
    // ---- sHp: horizontal box5 of y^2 (packed), transient in rcS space ----
    for (int i = tid; i < YP_ROWS*BP_COLS; i += NTHR){
        int r = i / BP_COLS, jj = i - r*BP_COLS;
        const u64* p = &sYp[r*YP_COLS + jj];
        u64 a = mul2_(p[0], p[0]);
        a = fma2_(p[1], p[1], a);
        a = fma2_(p[2], p[2], a);
        a = fma2_(p[3], p[3], a);
        a = fma2_(p[4], p[4], a);
        sHp[r*BP_COLS + jj] = a;
    }
    __syncthreads();
    // ---- sBp: vertical box5 of sHp ; xh: packed half2 raw x ----
    for (int i = tid; i < BP_ROWS*BP_COLS; i += NTHR){
        int rb = i / BP_COLS, jj = i - rb*BP_COLS;
        const u64* p = &sHp[rb*BP_COLS + jj];
        u64 bsum = add2_(add2_(add2_(p[0], p[BP_COLS]), add2_(p[2*BP_COLS], p[3*BP_COLS])), p[4*BP_COLS]);
        int base = ((r0 + rb - 5) & MASK) << 9;
        int gx = base | ((c0 + jj - 5) & MASK);
        int gy = base | ((c0 + jj + 27) & MASK);
        __half2 h0 = __floats2half2_rn(xb[gx],      xb[gy]);
        __half2 h1 = __floats2half2_rn(xb[HW+gx],   xb[HW+gy]);
        __half2 h2 = __floats2half2_rn(xb[2*HW+gx], xb[2*HW+gy]);
        xh[i]              = *(unsigned*)&h0;
        xh[XH_PLANE + i]   = *(unsigned*)&h1;
        xh[2*XH_PLANE + i] = *(unsigned*)&h2;
        sBp[i] = bsum;   // sBp disjoint from sHp(rcS) region -> safe before barrier
    }
    __syncthreads();

    const int lx   = threadIdx.x;
    const int trow = threadIdx.y * RPT;
    const float KEXP = -0.48089834696298783f;   // -1/(3*ln2)

    u64 Bp2[RPT];
    #pragma unroll
    for (int j = 0; j < RPT; j++)
        Bp2[j] = sBp[(trow+j+5)*BP_COLS + lx + 5];

    u64 aw2[RPT], a02[RPT], a12[RPT], a22[RPT];
    #pragma unroll
    for (int j = 0; j < RPT; j++){ aw2[j]=0; a02[j]=0; a12[j]=0; a22[j]=0; }

    #pragma unroll 1
    for (int sy = -5; sy <= 5; ++sy){
        // ---- Phase A: cooperative row correlations into rcS ----
        for (int t = tid; t < RC_ROWS*LANES; t += NTHR){
            int rr = t >> 5, cl = t & 31;
            const u64* cenp = &sYp[(rr+5)*YP_COLS + cl + 5];
            const u64* shp  = &sYp[(rr+5+sy)*YP_COLS + cl];
            u64 cen[5], sh[15];
            #pragma unroll
            for (int k = 0; k < 5; k++)  cen[k] = cenp[k];
            #pragma unroll
            for (int q = 0; q < 15; q++) sh[q]  = shp[q];
            u64* dst = &rcS[rr*RC_STRIDE + cl];
            #pragma unroll
            for (int s = 0; s < 11; s++){
                u64 r = mul2_(cen[0], sh[s]);
                r = fma2_(cen[1], sh[s+1], r);
                r = fma2_(cen[2], sh[s+2], r);
                r = fma2_(cen[3], sh[s+3], r);
                r = fma2_(cen[4], sh[s+4], r);
                dst[s*LANES] = r;
            }
        }
        __syncthreads();

        // ---- Phase B: sliding C window + weights + accumulation ----
        u64 C2[11];
        {
            const u64* p = &rcS[trow*RC_STRIDE + lx];
            #pragma unroll
            for (int s = 0; s < 11; s++){
                u64 c = add2_(p[s*LANES], p[(11+s)*LANES]);
                c = add2_(c, p[(22+s)*LANES]);
                c = add2_(c, p[(33+s)*LANES]);
                C2[s] = add2_(c, p[(44+s)*LANES]);
            }
        }
        #pragma unroll
        for (int j = 0; j < RPT; j++){
            if (j == 1){
                const u64* pn = &rcS[(trow+5)*RC_STRIDE + lx];
                const u64* po = &rcS[trow*RC_STRIDE + lx];
                #pragma unroll
                for (int s = 0; s < 11; s++)
                    C2[s] = fma2_(po[s*LANES], NEG1_2, add2_(C2[s], pn[s*LANES]));
            }
            const int br = trow + j + sy + 5;
            const u64* Brow = &sBp[br*BP_COLS + lx];
            u64 w2[11];
            #pragma unroll
            for (int s = 0; s < 11; s++){
                u64 D2 = fma2_(C2[s], NEG2_2, add2_(Bp2[j], Brow[s]));
                float d0 = fmaxf(lo_(D2), 0.f);
                float d1 = fmaxf(hi_(D2), 0.f);
                float w0 = fex2_a(fsqrt_a(d0) * KEXP);
                float w1 = fex2_a(fsqrt_a(d1) * KEXP);
                u64 w = pk_(w0, w1);
                w2[s] = w;
                aw2[j] = add2_(aw2[j], w);
            }
            #pragma unroll
            for (int ch = 0; ch < 3; ch++){
                const unsigned* Xrow = &xh[ch*XH_PLANE + br*BP_COLS + lx];
                u64 acc = (ch==0) ? a02[j] : (ch==1) ? a12[j] : a22[j];
                #pragma unroll
                for (int s = 0; s < 11; s++){
                    unsigned hx = Xrow[s];
                    float2 xv = __half22float2(*reinterpret_cast<const __half2*>(&hx));
                    acc = fma2_(w2[s], pk_(xv.x, xv.y), acc);
                }
                if (ch==0) a02[j] = acc; else if (ch==1) a12[j] = acc; else a22[j] = acc;
            }
        }
        __syncthreads();   // rcS reused next sy
    }

    // ---- epilogue: columns (c0+lx, c0+lx+32) ----
    #pragma unroll
    for (int j = 0; j < RPT; j++){
        float rw0 = frcp_a(lo_(aw2[j]));
        float rw1 = frcp_a(hi_(aw2[j]));
        int gr = r0 + trow + j;
        size_t o = (size_t)n*3*HW + ((size_t)gr << 9) + c0 + lx;
        out[o]           = __saturatef(lo_(a02[j])*rw0);
        out[o+32]        = __saturatef(hi_(a02[j])*rw1);
        out[o+HW]        = __saturatef(lo_(a12[j])*rw0);
        out[o+HW+32]     = __saturatef(hi_(a12[j])*rw1);
        out[o+2*HW]      = __saturatef(lo_(a22[j])*rw0);
        out[o+2*HW+32]   = __saturatef(hi_(a22[j])*rw1);
    }
}

extern "C" void kernel_launch(void* const* d_in, const int* in_sizes, int n_in,
                              void* d_out, int out_size){
    const float* x = (const float*)d_in[0];
    float* out = (float*)d_out;
    (void)in_sizes; (void)n_in; (void)out_size;

    cudaFuncSetAttribute(nlm_kernel, cudaFuncAttributeMaxDynamicSharedMemorySize, SMEM_BYTES);

    dim3 grid(WW/TILE_W, HH/TILE_H, NB);   // 8 x 32 x 2
    dim3 block(LANES, TYv);                // 256 threads
    nlm_kernel<<<grid, block, SMEM_BYTES>>>(x, out);
}

// round 12
// speedup vs baseline: 1.1455x; 1.1455x over previous
#include <cuda_runtime.h>
#include <cuda_fp16.h>

#define NB 2
#define HH 512
#define WW 512
#define MASK 511
#define HW (HH*WW)

#define LANES 16        // threads per row; thread owns cols (c, c+16)
#define TYv 8
#define RPT 2
#define TILE_W 32
#define TILE_H 16       // TYv * RPT
#define NTHR (LANES*TYv)

#define RC_ROWS 20      // template rows -2..17
#define YP_ROWS 30      // y rows -7..22
#define YP_COLS 30      // y col-pair index: logical col -7..22 (.x), +16 (.y)
#define BP_ROWS 26      // B/x rows -5..20
#define BP_COLS 26      // col-pair index: logical col -5..20 (.x), +16 (.y)

#define XH_STRIDE 40    // u32 row stride for xh: 2*40 = 80 = 16 mod 32 banks ->
                        // the two rows a warp touches hit disjoint bank halves
#define XH_PLANE (BP_ROWS*XH_STRIDE)   // 1040 u32 per channel

// offsets in u64 units
#define OFF_RC 0
#define OFF_YP (RC_ROWS*11*LANES)              // 3520
#define OFF_BP (OFF_YP + YP_ROWS*YP_COLS)      // 4420
#define OFF_XH (OFF_BP + BP_ROWS*BP_COLS)      // 5096
#define SMEM_U64 (OFF_XH + (3*XH_PLANE)/2)     // 5096 + 1560 = 6656
#define SMEM_BYTES (SMEM_U64*8)                // 53248

typedef unsigned long long u64;

__device__ __forceinline__ float lo_(u64 v){ return __uint_as_float((unsigned)v); }
__device__ __forceinline__ float hi_(u64 v){ return __uint_as_float((unsigned)(v >> 32)); }
__device__ __forceinline__ u64 pk_(float a, float b){ u64 r; asm("mov.b64 %0, {%1, %2};" : "=l"(r) : "f"(a), "f"(b)); return r; }
__device__ __forceinline__ u64 fma2_(u64 a, u64 b, u64 c){ u64 d; asm("fma.rn.f32x2 %0, %1, %2, %3;" : "=l"(d) : "l"(a), "l"(b), "l"(c)); return d; }
__device__ __forceinline__ u64 add2_(u64 a, u64 b){ u64 d; asm("add.rn.f32x2 %0, %1, %2;" : "=l"(d) : "l"(a), "l"(b)); return d; }
__device__ __forceinline__ u64 mul2_(u64 a, u64 b){ u64 d; asm("mul.rn.f32x2 %0, %1, %2;" : "=l"(d) : "l"(a), "l"(b)); return d; }
__device__ __forceinline__ float fsqrt_a(float x){ float y; asm("sqrt.approx.f32 %0, %1;" : "=f"(y) : "f"(x)); return y; }
__device__ __forceinline__ float fex2_a (float x){ float y; asm("ex2.approx.f32 %0, %1;"  : "=f"(y) : "f"(x)); return y; }
__device__ __forceinline__ float frcp_a (float x){ float y; asm("rcp.approx.f32 %0, %1;"  : "=f"(y) : "f"(x)); return y; }

#define NEG2_2 0xC0000000C0000000ULL   // {-2.f, -2.f}
#define NEG1_2 0xBF800000BF800000ULL   // {-1.f, -1.f}

__global__ void __launch_bounds__(NTHR, 4) nlm_kernel(const float* __restrict__ x,
                                                      float* __restrict__ out){
    extern __shared__ u64 smem[];
    u64* rcS = smem + OFF_RC;     // [rr][s][lane]
    u64* sYp = smem + OFF_YP;     // [r][jj] packed clipped luminance
    u64* sBp = smem + OFF_BP;     // [rb][jj] box5x5(y^2)
    unsigned* xh = (unsigned*)(smem + OFF_XH);  // [ch][rb][XH_STRIDE] half2 x
    u64* sHp = smem + OFF_RC;     // alias: transient hbox(y^2), [r][jj] 30x26

    const int n   = blockIdx.z;
    const int c0  = blockIdx.x * TILE_W;
    const int r0  = blockIdx.y * TILE_H;
    const int tid = threadIdx.y * LANES + threadIdx.x;
    const float* xb = x + (size_t)n*3*HW;

    // ---- sYp: packed clipped luminance, pair {col, col+16} ----
    for (int i = tid; i < YP_ROWS*YP_COLS; i += NTHR){
        int r = i / YP_COLS, jj = i - r*YP_COLS;
        int base = ((r0 + r - 7) & MASK) << 9;
        int gx = base | ((c0 + jj - 7) & MASK);
        int gy = base | ((c0 + jj + 9) & MASK);
        float l0 = 0.299f*__saturatef(xb[gx]) + 0.587f*__saturatef(xb[HW+gx]) + 0.114f*__saturatef(xb[2*HW+gx]);
        float l1 = 0.299f*__saturatef(xb[gy]) + 0.587f*__saturatef(xb[HW+gy]) + 0.114f*__saturatef(xb[2*HW+gy]);
        sYp[i] = pk_(l0, l1);
    }
    __syncthreads();
    // ---- sHp: horizontal box5 of y^2 (packed), transient in rcS space ----
    for (int i = tid; i < YP_ROWS*BP_COLS; i += NTHR){
        int r = i / BP_COLS, jj = i - r*BP_COLS;
        const u64* p = &sYp[r*YP_COLS + jj];
        u64 a = mul2_(p[0], p[0]);
        a = fma2_(p[1], p[1], a);
        a = fma2_(p[2], p[2], a);
        a = fma2_(p[3], p[3], a);
        a = fma2_(p[4], p[4], a);
        sHp[r*BP_COLS + jj] = a;
    }
    __syncthreads();
    // ---- sBp: vertical box5 of sHp ; xh: packed half2 raw x (padded stride) ----
    for (int i = tid; i < BP_ROWS*BP_COLS; i += NTHR){
        int rb = i / BP_COLS, jj = i - rb*BP_COLS;
        const u64* p = &sHp[rb*BP_COLS + jj];
        u64 bsum = add2_(add2_(add2_(p[0], p[BP_COLS]), add2_(p[2*BP_COLS], p[3*BP_COLS])), p[4*BP_COLS]);
        int base = ((r0 + rb - 5) & MASK) << 9;
        int gx = base | ((c0 + jj - 5) & MASK);
        int gy = base | ((c0 + jj + 11) & MASK);
        __half2 h0 = __floats2half2_rn(xb[gx],      xb[gy]);
        __half2 h1 = __floats2half2_rn(xb[HW+gx],   xb[HW+gy]);
        __half2 h2 = __floats2half2_rn(xb[2*HW+gx], xb[2*HW+gy]);
        int xi = rb*XH_STRIDE + jj;
        xh[xi]              = *(unsigned*)&h0;
        xh[XH_PLANE + xi]   = *(unsigned*)&h1;
        xh[2*XH_PLANE + xi] = *(unsigned*)&h2;
        sBp[i] = bsum;   // sBp disjoint from sHp(rcS) region -> safe before barrier
    }
    __syncthreads();

    const int lx   = threadIdx.x;
    const int trow = threadIdx.y * RPT;
    const float KEXP = -0.48089834696298783f;   // -1/(3*ln2)

    u64 Bp2[RPT];
    #pragma unroll
    for (int j = 0; j < RPT; j++)
        Bp2[j] = sBp[(trow+j+5)*BP_COLS + lx + 5];

    u64 aw2[RPT], a02[RPT], a12[RPT], a22[RPT];
    #pragma unroll
    for (int j = 0; j < RPT; j++){ aw2[j]=0; a02[j]=0; a12[j]=0; a22[j]=0; }

    #pragma unroll 1
    for (int sy = -5; sy <= 5; ++sy){
        // ---- Phase A: cooperative row correlations into rcS ----
        for (int t = tid; t < RC_ROWS*LANES; t += NTHR){
            int rr = t / LANES, cl = t - rr*LANES;
            const u64* cenp = &sYp[(rr+5)*YP_COLS + cl + 5];
            const u64* shp  = &sYp[(rr+5+sy)*YP_COLS + cl];
            u64 cen[5], sh[15];
            #pragma unroll
            for (int k = 0; k < 5; k++)  cen[k] = cenp[k];
            #pragma unroll
            for (int q = 0; q < 15; q++) sh[q]  = shp[q];
            u64* dst = &rcS[rr*11*LANES + cl];
            #pragma unroll
            for (int s = 0; s < 11; s++){
                u64 r = mul2_(cen[0], sh[s]);
                r = fma2_(cen[1], sh[s+1], r);
                r = fma2_(cen[2], sh[s+2], r);
                r = fma2_(cen[3], sh[s+3], r);
                r = fma2_(cen[4], sh[s+4], r);
                dst[s*LANES] = r;
            }
        }
        __syncthreads();

        // ---- Phase B: sliding C window + weights + accumulation ----
        u64 C2[11];
        {
            const u64* p = &rcS[trow*11*LANES + lx];
            #pragma unroll
            for (int s = 0; s < 11; s++){
                u64 c = add2_(p[s*LANES], p[(11+s)*LANES]);
                c = add2_(c, p[(22+s)*LANES]);
                c = add2_(c, p[(33+s)*LANES]);
                C2[s] = add2_(c, p[(44+s)*LANES]);
            }
        }
        #pragma unroll
        for (int j = 0; j < RPT; j++){
            if (j == 1){
                const u64* pn = &rcS[(trow+5)*11*LANES + lx];
                const u64* po = &rcS[trow*11*LANES + lx];
                #pragma unroll
                for (int s = 0; s < 11; s++)
                    C2[s] = fma2_(po[s*LANES], NEG1_2, add2_(C2[s], pn[s*LANES]));
            }
            const int br = trow + j + sy + 5;
            const u64* Brow = &sBp[br*BP_COLS + lx];
            u64 w2[11];
            #pragma unroll
            for (int s = 0; s < 11; s++){
                u64 D2 = fma2_(C2[s], NEG2_2, add2_(Bp2[j], Brow[s]));
                float d0 = fmaxf(lo_(D2), 0.f);
                float d1 = fmaxf(hi_(D2), 0.f);
                float w0 = fex2_a(fsqrt_a(d0) * KEXP);
                float w1 = fex2_a(fsqrt_a(d1) * KEXP);
                u64 w = pk_(w0, w1);
                w2[s] = w;
                aw2[j] = add2_(aw2[j], w);
            }
            #pragma unroll
            for (int ch = 0; ch < 3; ch++){
                const unsigned* Xrow = &xh[ch*XH_PLANE + br*XH_STRIDE + lx];
                u64 acc = (ch==0) ? a02[j] : (ch==1) ? a12[j] : a22[j];
                #pragma unroll
                for (int s = 0; s < 11; s++){
                    unsigned hx = Xrow[s];
                    float2 xv = __half22float2(*reinterpret_cast<const __half2*>(&hx));
                    acc = fma2_(w2[s], pk_(xv.x, xv.y), acc);
                }
                if (ch==0) a02[j] = acc; else if (ch==1) a12[j] = acc; else a22[j] = acc;
            }
        }
        __syncthreads();   // rcS reused next sy
    }

    // ---- epilogue: columns (c0+lx, c0+lx+16) ----
    #pragma unroll
    for (int j = 0; j < RPT; j++){
        float rw0 = frcp_a(lo_(aw2[j]));
        float rw1 = frcp_a(hi_(aw2[j]));
        int gr = r0 + trow + j;
        size_t o = (size_t)n*3*HW + ((size_t)gr << 9) + c0 + lx;
        out[o]           = __saturatef(lo_(a02[j])*rw0);
        out[o+16]        = __saturatef(hi_(a02[j])*rw1);
        out[o+HW]        = __saturatef(lo_(a12[j])*rw0);
        out[o+HW+16]     = __saturatef(hi_(a12[j])*rw1);
        out[o+2*HW]      = __saturatef(lo_(a22[j])*rw0);
        out[o+2*HW+16]   = __saturatef(hi_(a22[j])*rw1);
    }
}

extern "C" void kernel_launch(void* const* d_in, const int* in_sizes, int n_in,
                              void* d_out, int out_size){
    const float* x = (const float*)d_in[0];
    float* out = (float*)d_out;
    (void)in_sizes; (void)n_in; (void)out_size;

    cudaFuncSetAttribute(nlm_kernel, cudaFuncAttributeMaxDynamicSharedMemorySize, SMEM_BYTES);

    dim3 grid(WW/TILE_W, HH/TILE_H, NB);   // 16 x 32 x 2
    dim3 block(LANES, TYv);                // 128 threads
    nlm_kernel<<<grid, block, SMEM_BYTES>>>(x, out);
}

// round 13
// speedup vs baseline: 1.2001x; 1.0476x over previous
#include <cuda_runtime.h>
#include <cuda_fp16.h>

#define NB 2
#define HH 512
#define WW 512
#define MASK 511
#define HW (HH*WW)

#define LANES 16        // threads per row; thread owns cols (c, c+16)
#define TYv 8
#define RPT 2
#define TILE_W 32
#define TILE_H 16       // TYv * RPT
#define NTHR (LANES*TYv)

#define RC_ROWS 20      // template rows -2..17
#define YP_ROWS 30      // y rows -7..22
#define YP_COLS 30      // y col-pair index: logical col -7..22 (.x), +16 (.y)
#define BP_ROWS 26      // B/x rows -5..20
#define BP_COLS 26      // col-pair index: logical col -5..20 (.x), +16 (.y)

#define RC_STRIDE32 184 // u32 stride per rc row: 11*16=176 +8 pad; 184%32=24, 2*184%32=16
                        // -> dual-thread-row (Δ=2) warp reads hit disjoint bank halves (1 wf)

#define XH_STRIDE 40    // u32 row stride for xh: 2*40 = 80 = 16 mod 32 banks
#define XH_PLANE (BP_ROWS*XH_STRIDE)   // 1040 u32 per channel

// offsets in u64 units
#define OFF_RC 0
#define RC_U64 ((RC_ROWS*RC_STRIDE32)/2)       // 1840
#define OFF_YP RC_U64                          // 1840
#define OFF_BP (OFF_YP + YP_ROWS*YP_COLS)      // 2740
#define OFF_XH (OFF_BP + BP_ROWS*BP_COLS)      // 3416
#define SMEM_U64 (OFF_XH + (3*XH_PLANE)/2)     // 3416 + 1560 = 4976
#define SMEM_BYTES (SMEM_U64*8)                // 39808

typedef unsigned long long u64;

__device__ __forceinline__ float lo_(u64 v){ return __uint_as_float((unsigned)v); }
__device__ __forceinline__ float hi_(u64 v){ return __uint_as_float((unsigned)(v >> 32)); }
__device__ __forceinline__ u64 pk_(float a, float b){ u64 r; asm("mov.b64 %0, {%1, %2};" : "=l"(r) : "f"(a), "f"(b)); return r; }
__device__ __forceinline__ u64 fma2_(u64 a, u64 b, u64 c){ u64 d; asm("fma.rn.f32x2 %0, %1, %2, %3;" : "=l"(d) : "l"(a), "l"(b), "l"(c)); return d; }
__device__ __forceinline__ u64 add2_(u64 a, u64 b){ u64 d; asm("add.rn.f32x2 %0, %1, %2;" : "=l"(d) : "l"(a), "l"(b)); return d; }
__device__ __forceinline__ u64 mul2_(u64 a, u64 b){ u64 d; asm("mul.rn.f32x2 %0, %1, %2;" : "=l"(d) : "l"(a), "l"(b)); return d; }
__device__ __forceinline__ float fsqrt_a(float x){ float y; asm("sqrt.approx.f32 %0, %1;" : "=f"(y) : "f"(x)); return y; }
__device__ __forceinline__ float fex2_a (float x){ float y; asm("ex2.approx.f32 %0, %1;"  : "=f"(y) : "f"(x)); return y; }
__device__ __forceinline__ float frcp_a (float x){ float y; asm("rcp.approx.f32 %0, %1;"  : "=f"(y) : "f"(x)); return y; }

#define NEG2_2 0xC0000000C0000000ULL   // {-2.f, -2.f}
#define NEG1_2 0xBF800000BF800000ULL   // {-1.f, -1.f}

__global__ void __launch_bounds__(NTHR, 5) nlm_kernel(const float* __restrict__ x,
                                                      float* __restrict__ out){
    extern __shared__ u64 smem[];
    unsigned* rc16 = (unsigned*)(smem + OFF_RC);  // [rr][s*16+lane] half2 rc, stride RC_STRIDE32
    u64* sYp = smem + OFF_YP;     // [r][jj] packed clipped luminance
    u64* sBp = smem + OFF_BP;     // [rb][jj] box5x5(y^2)
    unsigned* xh = (unsigned*)(smem + OFF_XH);  // [ch][rb][XH_STRIDE] half2 x
    u64* sHp = smem + OFF_RC;     // alias: transient hbox(y^2), [r][jj] 30x26 (6240B < rc16 14720B)

    const int n   = blockIdx.z;
    const int c0  = blockIdx.x * TILE_W;
    const int r0  = blockIdx.y * TILE_H;
    const int tid = threadIdx.y * LANES + threadIdx.x;
    const float* xb = x + (size_t)n*3*HW;

    // ---- sYp: packed clipped luminance, pair {col, col+16} ----
    for (int i = tid; i < YP_ROWS*YP_COLS; i += NTHR){
        int r = i / YP_COLS, jj = i - r*YP_COLS;
        int base = ((r0 + r - 7) & MASK) << 9;
        int gx = base | ((c0 + jj - 7) & MASK);
        int gy = base | ((c0 + jj + 9) & MASK);
        float l0 = 0.299f*__saturatef(xb[gx]) + 0.587f*__saturatef(xb[HW+gx]) + 0.114f*__saturatef(xb[2*HW+gx]);
        float l1 = 0.299f*__saturatef(xb[gy]) + 0.587f*__saturatef(xb[HW+gy]) + 0.114f*__saturatef(xb[2*HW+gy]);
        sYp[i] = pk_(l0, l1);
    }
    __syncthreads();
    // ---- sHp: horizontal box5 of y^2 (packed), transient in rc16 space ----
    for (int i = tid; i < YP_ROWS*BP_COLS; i += NTHR){
        int r = i / BP_COLS, jj = i - r*BP_COLS;
        const u64* p = &sYp[r*YP_COLS + jj];
        u64 a = mul2_(p[0], p[0]);
        a = fma2_(p[1], p[1], a);
        a = fma2_(p[2], p[2], a);
        a = fma2_(p[3], p[3], a);
        a = fma2_(p[4], p[4], a);
        sHp[r*BP_COLS + jj] = a;
    }
    __syncthreads();
    // ---- sBp: vertical box5 of sHp ; xh: packed half2 raw x (padded stride) ----
    for (int i = tid; i < BP_ROWS*BP_COLS; i += NTHR){
        int rb = i / BP_COLS, jj = i - rb*BP_COLS;
        const u64* p = &sHp[rb*BP_COLS + jj];
        u64 bsum = add2_(add2_(add2_(p[0], p[BP_COLS]), add2_(p[2*BP_COLS], p[3*BP_COLS])), p[4*BP_COLS]);
        int base = ((r0 + rb - 5) & MASK) << 9;
        int gx = base | ((c0 + jj - 5) & MASK);
        int gy = base | ((c0 + jj + 11) & MASK);
        __half2 h0 = __floats2half2_rn(xb[gx],      xb[gy]);
        __half2 h1 = __floats2half2_rn(xb[HW+gx],   xb[HW+gy]);
        __half2 h2 = __floats2half2_rn(xb[2*HW+gx], xb[2*HW+gy]);
        int xi = rb*XH_STRIDE + jj;
        xh[xi]              = *(unsigned*)&h0;
        xh[XH_PLANE + xi]   = *(unsigned*)&h1;
        xh[2*XH_PLANE + xi] = *(unsigned*)&h2;
        sBp[i] = bsum;   // sBp disjoint from sHp(rc16) region -> safe before barrier
    }
    __syncthreads();

    const int lx   = threadIdx.x;
    const int trow = threadIdx.y * RPT;
    const float KEXP = -0.48089834696298783f;   // -1/(3*ln2)

    u64 Bp2[RPT];
    #pragma unroll
    for (int j = 0; j < RPT; j++)
        Bp2[j] = sBp[(trow+j+5)*BP_COLS + lx + 5];

    u64 aw2[RPT], a02[RPT], a12[RPT], a22[RPT];
    #pragma unroll
    for (int j = 0; j < RPT; j++){ aw2[j]=0; a02[j]=0; a12[j]=0; a22[j]=0; }

    #pragma unroll 1
    for (int sy = -5; sy <= 5; ++sy){
        // ---- Phase A: cooperative row correlations into rc16 (half2) ----
        for (int t = tid; t < RC_ROWS*LANES; t += NTHR){
            int rr = t / LANES, cl = t - rr*LANES;
            const u64* cenp = &sYp[(rr+5)*YP_COLS + cl + 5];
            const u64* shp  = &sYp[(rr+5+sy)*YP_COLS + cl];
            u64 cen[5], sh[15];
            #pragma unroll
            for (int k = 0; k < 5; k++)  cen[k] = cenp[k];
            #pragma unroll
            for (int q = 0; q < 15; q++) sh[q]  = shp[q];
            unsigned* dst = &rc16[rr*RC_STRIDE32 + cl];
            #pragma unroll
            for (int s = 0; s < 11; s++){
                u64 r = mul2_(cen[0], sh[s]);
                r = fma2_(cen[1], sh[s+1], r);
                r = fma2_(cen[2], sh[s+2], r);
                r = fma2_(cen[3], sh[s+3], r);
                r = fma2_(cen[4], sh[s+4], r);
                __half2 h = __floats2half2_rn(lo_(r), hi_(r));
                dst[s*LANES] = *(unsigned*)&h;
            }
        }
        __syncthreads();

        // ---- Phase B: sliding C window (half2) + weights + accumulation ----
        __half2 Ch[11];
        {
            const unsigned* p = &rc16[trow*RC_STRIDE32 + lx];
            #pragma unroll
            for (int s = 0; s < 11; s++){
                unsigned v0 = p[s*LANES];
                unsigned v1 = p[RC_STRIDE32   + s*LANES];
                unsigned v2 = p[2*RC_STRIDE32 + s*LANES];
                unsigned v3 = p[3*RC_STRIDE32 + s*LANES];
                unsigned v4 = p[4*RC_STRIDE32 + s*LANES];
                __half2 c = __hadd2(*(__half2*)&v0, *(__half2*)&v1);
                c = __hadd2(c, *(__half2*)&v2);
                c = __hadd2(c, *(__half2*)&v3);
                Ch[s] = __hadd2(c, *(__half2*)&v4);
            }
        }
        #pragma unroll
        for (int j = 0; j < RPT; j++){
            if (j == 1){
                const unsigned* pn = &rc16[(trow+5)*RC_STRIDE32 + lx];
                const unsigned* po = &rc16[trow*RC_STRIDE32 + lx];
                #pragma unroll
                for (int s = 0; s < 11; s++){
                    unsigned nv = pn[s*LANES], ov = po[s*LANES];
                    Ch[s] = __hadd2(Ch[s], __hsub2(*(__half2*)&nv, *(__half2*)&ov));
                }
            }
            const int br = trow + j + sy + 5;
            const u64* Brow = &sBp[br*BP_COLS + lx];
            u64 w2[11];
            #pragma unroll
            for (int s = 0; s < 11; s++){
                float2 cf = __half22float2(Ch[s]);
                u64 D2 = fma2_(pk_(cf.x, cf.y), NEG2_2, add2_(Bp2[j], Brow[s]));
                float d0 = fmaxf(lo_(D2), 0.f);
                float d1 = fmaxf(hi_(D2), 0.f);
                float w0 = fex2_a(fsqrt_a(d0) * KEXP);
                float w1 = fex2_a(fsqrt_a(d1) * KEXP);
                u64 w = pk_(w0, w1);
                w2[s] = w;
                aw2[j] = add2_(aw2[j], w);
            }
            #pragma unroll
            for (int ch = 0; ch < 3; ch++){
                const unsigned* Xrow = &xh[ch*XH_PLANE + br*XH_STRIDE + lx];
                u64 acc = (ch==0) ? a02[j] : (ch==1) ? a12[j] : a22[j];
                #pragma unroll
                for (int s = 0; s < 11; s++){
                    unsigned hx = Xrow[s];
                    float2 xv = __half22float2(*reinterpret_cast<const __half2*>(&hx));
                    acc = fma2_(w2[s], pk_(xv.x, xv.y), acc);
                }
                if (ch==0) a02[j] = acc; else if (ch==1) a12[j] = acc; else a22[j] = acc;
            }
        }
        __syncthreads();   // rc16 reused next sy
    }

    // ---- epilogue: columns (c0+lx, c0+lx+16) ----
    #pragma unroll
    for (int j = 0; j < RPT; j++){
        float rw0 = frcp_a(lo_(aw2[j]));
        float rw1 = frcp_a(hi_(aw2[j]));
        int gr = r0 + trow + j;
        size_t o = (size_t)n*3*HW + ((size_t)gr << 9) + c0 + lx;
        out[o]           = __saturatef(lo_(a02[j])*rw0);
        out[o+16]        = __saturatef(hi_(a02[j])*rw1);
        out[o+HW]        = __saturatef(lo_(a12[j])*rw0);
        out[o+HW+16]     = __saturatef(hi_(a12[j])*rw1);
        out[o+2*HW]      = __saturatef(lo_(a22[j])*rw0);
        out[o+2*HW+16]   = __saturatef(hi_(a22[j])*rw1);
    }
}

extern "C" void kernel_launch(void* const* d_in, const int* in_sizes, int n_in,
                              void* d_out, int out_size){
    const float* x = (const float*)d_in[0];
    float* out = (float*)d_out;
    (void)in_sizes; (void)n_in; (void)out_size;

    cudaFuncSetAttribute(nlm_kernel, cudaFuncAttributeMaxDynamicSharedMemorySize, SMEM_BYTES);

    dim3 grid(WW/TILE_W, HH/TILE_H, NB);   // 16 x 32 x 2
    dim3 block(LANES, TYv);                // 128 threads
    nlm_kernel<<<grid, block, SMEM_BYTES>>>(x, out);
}

// round 14
// speedup vs baseline: 1.2643x; 1.0535x over previous
#include <cuda_runtime.h>
#include <cuda_fp16.h>

#define NB 2
#define HH 512
#define WW 512
#define MASK 511
#define HW (HH*WW)

#define LANES 16        // threads per row; thread owns cols (c, c+16)
#define TYv 8
#define RPT 2
#define TILE_W 32
#define TILE_H 16       // TYv * RPT
#define NTHR (LANES*TYv)

#define RC_ROWS 20      // template rows -2..17
#define YP_ROWS 30      // y rows -7..22
#define YP_COLS 30      // logical col-pair entries: col -7..22 (.x), +16 (.y)
#define YP_STRIDE 48    // u32 stride: 48 = 16 mod 32 -> Δ=1-row warp halves on disjoint banks (1 wf)
#define BP_ROWS 26      // B/x rows -5..20
#define BP_COLS 26      // col-pair entries: col -5..20 (.x), +16 (.y)

#define RC_STRIDE32 184 // 2*184 = 16 mod 32 -> Δ=2-row Phase-B reads 1 wf

#define XH_STRIDE 40    // 2*40 = 16 mod 32 -> 1 wf
#define XH_PLANE (BP_ROWS*XH_STRIDE)   // 1040 u32 per channel

// layout in u32 units
#define OFF_RC32 0
#define OFF_YP32 (RC_ROWS*RC_STRIDE32)          // 3680
#define OFF_BP32 (OFF_YP32 + YP_ROWS*YP_STRIDE) // 3680+1440 = 5120 (8B aligned)
#define OFF_XH32 (OFF_BP32 + 2*BP_ROWS*BP_COLS) // 5120+1352 = 6472
#define SMEM_U32 (OFF_XH32 + 3*XH_PLANE)        // 6472+3120 = 9592
#define SMEM_BYTES (SMEM_U32*4)                 // 38368

typedef unsigned long long u64;

__device__ __forceinline__ float lo_(u64 v){ return __uint_as_float((unsigned)v); }
__device__ __forceinline__ float hi_(u64 v){ return __uint_as_float((unsigned)(v >> 32)); }
__device__ __forceinline__ u64 pk_(float a, float b){ u64 r; asm("mov.b64 %0, {%1, %2};" : "=l"(r) : "f"(a), "f"(b)); return r; }
__device__ __forceinline__ u64 fma2_(u64 a, u64 b, u64 c){ u64 d; asm("fma.rn.f32x2 %0, %1, %2, %3;" : "=l"(d) : "l"(a), "l"(b), "l"(c)); return d; }
__device__ __forceinline__ u64 add2_(u64 a, u64 b){ u64 d; asm("add.rn.f32x2 %0, %1, %2;" : "=l"(d) : "l"(a), "l"(b)); return d; }
__device__ __forceinline__ u64 mul2_(u64 a, u64 b){ u64 d; asm("mul.rn.f32x2 %0, %1, %2;" : "=l"(d) : "l"(a), "l"(b)); return d; }
__device__ __forceinline__ float fsqrt_a(float x){ float y; asm("sqrt.approx.f32 %0, %1;" : "=f"(y) : "f"(x)); return y; }
__device__ __forceinline__ float fex2_a (float x){ float y; asm("ex2.approx.f32 %0, %1;"  : "=f"(y) : "f"(x)); return y; }
__device__ __forceinline__ float frcp_a (float x){ float y; asm("rcp.approx.f32 %0, %1;"  : "=f"(y) : "f"(x)); return y; }

#define NEG2_2 0xC0000000C0000000ULL   // {-2.f, -2.f}

__global__ void __launch_bounds__(NTHR, 5) nlm_kernel(const float* __restrict__ x,
                                                      float* __restrict__ out){
    extern __shared__ unsigned smem32[];
    unsigned* rc16 = smem32 + OFF_RC32;            // [rr][s*16+lane] half2 rc
    unsigned* sYh  = smem32 + OFF_YP32;            // [r][YP_STRIDE] half2 luminance
    u64*      sBp  = (u64*)(smem32 + OFF_BP32);    // [rb][jj] f32x2 box5x5(y^2)
    unsigned* xh   = smem32 + OFF_XH32;            // [ch][rb][XH_STRIDE] half2 x
    u64*      sHp  = (u64*)(smem32 + OFF_RC32);    // alias: transient f32 hbox, 30x26 u64 (6240B < rc 14720B)

    const int n   = blockIdx.z;
    const int c0  = blockIdx.x * TILE_W;
    const int r0  = blockIdx.y * TILE_H;
    const int tid = threadIdx.y * LANES + threadIdx.x;
    const float* xb = x + (size_t)n*3*HW;

    // ---- sYh: packed clipped luminance in half2, pair {col, col+16} ----
    for (int i = tid; i < YP_ROWS*YP_COLS; i += NTHR){
        int r = i / YP_COLS, jj = i - r*YP_COLS;
        int base = ((r0 + r - 7) & MASK) << 9;
        int gx = base | ((c0 + jj - 7) & MASK);
        int gy = base | ((c0 + jj + 9) & MASK);
        float l0 = 0.299f*__saturatef(xb[gx]) + 0.587f*__saturatef(xb[HW+gx]) + 0.114f*__saturatef(xb[2*HW+gx]);
        float l1 = 0.299f*__saturatef(xb[gy]) + 0.587f*__saturatef(xb[HW+gy]) + 0.114f*__saturatef(xb[2*HW+gy]);
        __half2 h = __floats2half2_rn(l0, l1);
        sYh[r*YP_STRIDE + jj] = *(unsigned*)&h;
    }
    __syncthreads();
    // ---- sHp: horizontal box5 of (half-rounded y)^2, f32, transient in rc region ----
    for (int i = tid; i < YP_ROWS*BP_COLS; i += NTHR){
        int r = i / BP_COLS, jj = i - r*BP_COLS;
        const unsigned* p = &sYh[r*YP_STRIDE + jj];
        u64 a = 0;
        #pragma unroll
        for (int u = 0; u < 5; u++){
            unsigned hv = p[u];
            float2 v = __half22float2(*(__half2*)&hv);
            u64 vp = pk_(v.x, v.y);
            a = fma2_(vp, vp, a);
        }
        sHp[r*BP_COLS + jj] = a;
    }
    __syncthreads();
    // ---- sBp: vertical box5 of sHp (f32) ; xh: packed half2 raw x ----
    for (int i = tid; i < BP_ROWS*BP_COLS; i += NTHR){
        int rb = i / BP_COLS, jj = i - rb*BP_COLS;
        const u64* p = &sHp[rb*BP_COLS + jj];
        u64 bsum = add2_(add2_(add2_(p[0], p[BP_COLS]), add2_(p[2*BP_COLS], p[3*BP_COLS])), p[4*BP_COLS]);
        int base = ((r0 + rb - 5) & MASK) << 9;
        int gx = base | ((c0 + jj - 5) & MASK);
        int gy = base | ((c0 + jj + 11) & MASK);
        __half2 h0 = __floats2half2_rn(xb[gx],      xb[gy]);
        __half2 h1 = __floats2half2_rn(xb[HW+gx],   xb[HW+gy]);
        __half2 h2 = __floats2half2_rn(xb[2*HW+gx], xb[2*HW+gy]);
        int xi = rb*XH_STRIDE + jj;
        xh[xi]              = *(unsigned*)&h0;
        xh[XH_PLANE + xi]   = *(unsigned*)&h1;
        xh[2*XH_PLANE + xi] = *(unsigned*)&h2;
        sBp[i] = bsum;   // sBp region disjoint from sHp alias -> safe before barrier
    }
    __syncthreads();

    const int lx   = threadIdx.x;
    const int trow = threadIdx.y * RPT;
    const float KEXP = -0.48089834696298783f;   // -1/(3*ln2)

    u64 Bp2[RPT];
    #pragma unroll
    for (int j = 0; j < RPT; j++)
        Bp2[j] = sBp[(trow+j+5)*BP_COLS + lx + 5];

    u64 aw2[RPT], a02[RPT], a12[RPT], a22[RPT];
    #pragma unroll
    for (int j = 0; j < RPT; j++){ aw2[j]=0; a02[j]=0; a12[j]=0; a22[j]=0; }

    #pragma unroll 1
    for (int sy = -5; sy <= 5; ++sy){
        // ---- Phase A: cooperative row correlations in half2 (HMUL2/HFMA2) ----
        for (int t = tid; t < RC_ROWS*LANES; t += NTHR){
            int rr = t / LANES, cl = t - rr*LANES;
            const unsigned* cenp = &sYh[(rr+5)*YP_STRIDE + cl + 5];
            const unsigned* shp  = &sYh[(rr+5+sy)*YP_STRIDE + cl];
            __half2 cen[5], sh[15];
            #pragma unroll
            for (int k = 0; k < 5; k++){ unsigned v = cenp[k]; cen[k] = *(__half2*)&v; }
            #pragma unroll
            for (int q = 0; q < 15; q++){ unsigned v = shp[q]; sh[q] = *(__half2*)&v; }
            unsigned* dst = &rc16[rr*RC_STRIDE32 + cl];
            #pragma unroll
            for (int s = 0; s < 11; s++){
                __half2 r = __hmul2(cen[0], sh[s]);
                r = __hfma2(cen[1], sh[s+1], r);
                r = __hfma2(cen[2], sh[s+2], r);
                r = __hfma2(cen[3], sh[s+3], r);
                r = __hfma2(cen[4], sh[s+4], r);
                dst[s*LANES] = *(unsigned*)&r;
            }
        }
        __syncthreads();

        // ---- Phase B: sliding C window (half2) + weights + accumulation ----
        __half2 Ch[11];
        {
            const unsigned* p = &rc16[trow*RC_STRIDE32 + lx];
            #pragma unroll
            for (int s = 0; s < 11; s++){
                unsigned v0 = p[s*LANES];
                unsigned v1 = p[RC_STRIDE32   + s*LANES];
                unsigned v2 = p[2*RC_STRIDE32 + s*LANES];
                unsigned v3 = p[3*RC_STRIDE32 + s*LANES];
                unsigned v4 = p[4*RC_STRIDE32 + s*LANES];
                __half2 c = __hadd2(*(__half2*)&v0, *(__half2*)&v1);
                c = __hadd2(c, *(__half2*)&v2);
                c = __hadd2(c, *(__half2*)&v3);
                Ch[s] = __hadd2(c, *(__half2*)&v4);
            }
        }
        #pragma unroll
        for (int j = 0; j < RPT; j++){
            if (j == 1){
                const unsigned* pn = &rc16[(trow+5)*RC_STRIDE32 + lx];
                const unsigned* po = &rc16[trow*RC_STRIDE32 + lx];
                #pragma unroll
                for (int s = 0; s < 11; s++){
                    unsigned nv = pn[s*LANES], ov = po[s*LANES];
                    Ch[s] = __hadd2(Ch[s], __hsub2(*(__half2*)&nv, *(__half2*)&ov));
                }
            }
            const int br = trow + j + sy + 5;
            const u64* Brow = &sBp[br*BP_COLS + lx];
            u64 w2[11];
            #pragma unroll
            for (int s = 0; s < 11; s++){
                float2 cf = __half22float2(Ch[s]);
                u64 D2 = fma2_(pk_(cf.x, cf.y), NEG2_2, add2_(Bp2[j], Brow[s]));
                float d0 = fmaxf(lo_(D2), 0.f);
                float d1 = fmaxf(hi_(D2), 0.f);
                float w0 = fex2_a(fsqrt_a(d0) * KEXP);
                float w1 = fex2_a(fsqrt_a(d1) * KEXP);
                u64 w = pk_(w0, w1);
                w2[s] = w;
                aw2[j] = add2_(aw2[j], w);
            }
            #pragma unroll
            for (int ch = 0; ch < 3; ch++){
                const unsigned* Xrow = &xh[ch*XH_PLANE + br*XH_STRIDE + lx];
                u64 acc = (ch==0) ? a02[j] : (ch==1) ? a12[j] : a22[j];
                #pragma unroll
                for (int s = 0; s < 11; s++){
                    unsigned hx = Xrow[s];
                    float2 xv = __half22float2(*reinterpret_cast<const __half2*>(&hx));
                    acc = fma2_(w2[s], pk_(xv.x, xv.y), acc);
                }
                if (ch==0) a02[j] = acc; else if (ch==1) a12[j] = acc; else a22[j] = acc;
            }
        }
        __syncthreads();   // rc16 reused next sy
    }

    // ---- epilogue: columns (c0+lx, c0+lx+16) ----
    #pragma unroll
    for (int j = 0; j < RPT; j++){
        float rw0 = frcp_a(lo_(aw2[j]));
        float rw1 = frcp_a(hi_(aw2[j]));
        int gr = r0 + trow + j;
        size_t o = (size_t)n*3*HW + ((size_t)gr << 9) + c0 + lx;
        out[o]           = __saturatef(lo_(a02[j])*rw0);
        out[o+16]        = __saturatef(hi_(a02[j])*rw1);
        out[o+HW]        = __saturatef(lo_(a12[j])*rw0);
        out[o+HW+16]     = __saturatef(hi_(a12[j])*rw1);
        out[o+2*HW]      = __saturatef(lo_(a22[j])*rw0);
        out[o+2*HW+16]   = __saturatef(hi_(a22[j])*rw1);
    }
}

extern "C" void kernel_launch(void* const* d_in, const int* in_sizes, int n_in,
                              void* d_out, int out_size){
    const float* x = (const float*)d_in[0];
    float* out = (float*)d_out;
    (void)in_sizes; (void)n_in; (void)out_size;

    cudaFuncSetAttribute(nlm_kernel, cudaFuncAttributeMaxDynamicSharedMemorySize, SMEM_BYTES);

    dim3 grid(WW/TILE_W, HH/TILE_H, NB);   // 16 x 32 x 2
    dim3 block(LANES, TYv);                // 128 threads
    nlm_kernel<<<grid, block, SMEM_BYTES>>>(x, out);
}

// round 15
// speedup vs baseline: 1.3810x; 1.0923x over previous
#include <cuda_runtime.h>
#include <cuda_fp16.h>

#define NB 2
#define HH 512
#define WW 512
#define MASK 511
#define HW (HH*WW)

#define LANES 16        // threads per row; thread owns cols (c, c+16)
#define TYv 8
#define RPT 2
#define TILE_W 32
#define TILE_H 16       // TYv * RPT
#define NTHR (LANES*TYv)

#define RC_ROWS 20      // template rows -2..17
#define YP_ROWS 30      // y rows -7..22
#define YP_COLS 30      // logical col-pair entries: col -7..22 (.x), +16 (.y)
#define YP_STRIDE 48    // u32 stride: 48 = 16 mod 32 -> Δ=1-row warp halves on disjoint banks (1 wf)
#define BP_ROWS 26      // B/x rows -5..20
#define BP_COLS 26      // col-pair entries: col -5..20 (.x), +16 (.y)

#define RC_STRIDE32 184 // 2*184 = 16 mod 32 -> Δ=2-row Phase-B reads 1 wf

#define XH_STRIDE 40    // 2*40 = 16 mod 32 -> 1 wf
#define XH_PLANE (BP_ROWS*XH_STRIDE)   // 1040 u32 per channel

// layout in u32 units
#define OFF_RC32 0
#define OFF_YP32 (RC_ROWS*RC_STRIDE32)          // 3680
#define OFF_BP32 (OFF_YP32 + YP_ROWS*YP_STRIDE) // 3680+1440 = 5120 (8B aligned)
#define OFF_XH32 (OFF_BP32 + 2*BP_ROWS*BP_COLS) // 5120+1352 = 6472
#define SMEM_U32 (OFF_XH32 + 3*XH_PLANE)        // 6472+3120 = 9592
#define SMEM_BYTES (SMEM_U32*4)                 // 38368

typedef unsigned long long u64;

__device__ __forceinline__ float lo_(u64 v){ return __uint_as_float((unsigned)v); }
__device__ __forceinline__ float hi_(u64 v){ return __uint_as_float((unsigned)(v >> 32)); }
__device__ __forceinline__ u64 pk_(float a, float b){ u64 r; asm("mov.b64 %0, {%1, %2};" : "=l"(r) : "f"(a), "f"(b)); return r; }
__device__ __forceinline__ u64 fma2_(u64 a, u64 b, u64 c){ u64 d; asm("fma.rn.f32x2 %0, %1, %2, %3;" : "=l"(d) : "l"(a), "l"(b), "l"(c)); return d; }
__device__ __forceinline__ u64 add2_(u64 a, u64 b){ u64 d; asm("add.rn.f32x2 %0, %1, %2;" : "=l"(d) : "l"(a), "l"(b)); return d; }
__device__ __forceinline__ u64 mul2_(u64 a, u64 b){ u64 d; asm("mul.rn.f32x2 %0, %1, %2;" : "=l"(d) : "l"(a), "l"(b)); return d; }
__device__ __forceinline__ float fsqrt_a(float x){ float y; asm("sqrt.approx.f32 %0, %1;" : "=f"(y) : "f"(x)); return y; }
__device__ __forceinline__ float fex2_a (float x){ float y; asm("ex2.approx.f32 %0, %1;"  : "=f"(y) : "f"(x)); return y; }
__device__ __forceinline__ float frcp_a (float x){ float y; asm("rcp.approx.f32 %0, %1;"  : "=f"(y) : "f"(x)); return y; }

#define NEG2_2 0xC0000000C0000000ULL   // {-2.f, -2.f}

__global__ void __launch_bounds__(NTHR, 5) nlm_kernel(const float* __restrict__ x,
                                                      float* __restrict__ out){
    extern __shared__ unsigned smem32[];
    unsigned* rc16 = smem32 + OFF_RC32;            // [rr][s*16+lane] half2 rc
    unsigned* sYh  = smem32 + OFF_YP32;            // [r][YP_STRIDE] half2 luminance
    u64*      sBp  = (u64*)(smem32 + OFF_BP32);    // [rb][jj] f32x2 box5x5(y^2)
    unsigned* xh   = smem32 + OFF_XH32;            // [ch][rb][XH_STRIDE] half2 x
    u64*      sHp  = (u64*)(smem32 + OFF_RC32);    // alias: transient f32 hbox, 30x26 u64

    const int n   = blockIdx.z;
    const int c0  = blockIdx.x * TILE_W;
    const int r0  = blockIdx.y * TILE_H;
    const int tid = threadIdx.y * LANES + threadIdx.x;
    const float* xb = x + (size_t)n*3*HW;

    // ---- sYh: packed clipped luminance in half2, pair {col, col+16} ----
    for (int i = tid; i < YP_ROWS*YP_COLS; i += NTHR){
        int r = i / YP_COLS, jj = i - r*YP_COLS;
        int base = ((r0 + r - 7) & MASK) << 9;
        int gx = base | ((c0 + jj - 7) & MASK);
        int gy = base | ((c0 + jj + 9) & MASK);
        float l0 = 0.299f*__saturatef(xb[gx]) + 0.587f*__saturatef(xb[HW+gx]) + 0.114f*__saturatef(xb[2*HW+gx]);
        float l1 = 0.299f*__saturatef(xb[gy]) + 0.587f*__saturatef(xb[HW+gy]) + 0.114f*__saturatef(xb[2*HW+gy]);
        __half2 h = __floats2half2_rn(l0, l1);
        sYh[r*YP_STRIDE + jj] = *(unsigned*)&h;
    }
    __syncthreads();
    // ---- sHp: horizontal box5 of (half-rounded y)^2, f32, transient in rc region ----
    for (int i = tid; i < YP_ROWS*BP_COLS; i += NTHR){
        int r = i / BP_COLS, jj = i - r*BP_COLS;
        const unsigned* p = &sYh[r*YP_STRIDE + jj];
        u64 a = 0;
        #pragma unroll
        for (int u = 0; u < 5; u++){
            unsigned hv = p[u];
            float2 v = __half22float2(*(__half2*)&hv);
            u64 vp = pk_(v.x, v.y);
            a = fma2_(vp, vp, a);
        }
        sHp[r*BP_COLS + jj] = a;
    }
    __syncthreads();
    // ---- sBp: vertical box5 of sHp (f32) ; xh: packed half2 raw x ----
    for (int i = tid; i < BP_ROWS*BP_COLS; i += NTHR){
        int rb = i / BP_COLS, jj = i - rb*BP_COLS;
        const u64* p = &sHp[rb*BP_COLS + jj];
        u64 bsum = add2_(add2_(add2_(p[0], p[BP_COLS]), add2_(p[2*BP_COLS], p[3*BP_COLS])), p[4*BP_COLS]);
        int base = ((r0 + rb - 5) & MASK) << 9;
        int gx = base | ((c0 + jj - 5) & MASK);
        int gy = base | ((c0 + jj + 11) & MASK);
        __half2 h0 = __floats2half2_rn(xb[gx],      xb[gy]);
        __half2 h1 = __floats2half2_rn(xb[HW+gx],   xb[HW+gy]);
        __half2 h2 = __floats2half2_rn(xb[2*HW+gx], xb[2*HW+gy]);
        int xi = rb*XH_STRIDE + jj;
        xh[xi]              = *(unsigned*)&h0;
        xh[XH_PLANE + xi]   = *(unsigned*)&h1;
        xh[2*XH_PLANE + xi] = *(unsigned*)&h2;
        sBp[i] = bsum;   // sBp region disjoint from sHp alias -> safe before barrier
    }
    __syncthreads();

    const int lx   = threadIdx.x;
    const int trow = threadIdx.y * RPT;
    const float KEXP = -0.48089834696298783f;   // -1/(3*ln2)

    u64 Bp2[RPT];
    #pragma unroll
    for (int j = 0; j < RPT; j++)
        Bp2[j] = sBp[(trow+j+5)*BP_COLS + lx + 5];

    u64 aw2[RPT], a02[RPT], a12[RPT], a22[RPT];
    #pragma unroll
    for (int j = 0; j < RPT; j++){ aw2[j]=0; a02[j]=0; a12[j]=0; a22[j]=0; }

    #pragma unroll 1
    for (int sy = -5; sy <= 5; ++sy){
        // ---- Phase A: cooperative row correlations in half2 (HMUL2/HFMA2) ----
        for (int t = tid; t < RC_ROWS*LANES; t += NTHR){
            int rr = t / LANES, cl = t - rr*LANES;
            const unsigned* cenp = &sYh[(rr+5)*YP_STRIDE + cl + 5];
            const unsigned* shp  = &sYh[(rr+5+sy)*YP_STRIDE + cl];
            __half2 cen[5], sh[15];
            #pragma unroll
            for (int k = 0; k < 5; k++){ unsigned v = cenp[k]; cen[k] = *(__half2*)&v; }
            #pragma unroll
            for (int q = 0; q < 15; q++){ unsigned v = shp[q]; sh[q] = *(__half2*)&v; }
            unsigned* dst = &rc16[rr*RC_STRIDE32 + cl];
            #pragma unroll
            for (int s = 0; s < 11; s++){
                __half2 r = __hmul2(cen[0], sh[s]);
                r = __hfma2(cen[1], sh[s+1], r);
                r = __hfma2(cen[2], sh[s+2], r);
                r = __hfma2(cen[3], sh[s+3], r);
                r = __hfma2(cen[4], sh[s+4], r);
                dst[s*LANES] = *(unsigned*)&r;
            }
        }
        __syncthreads();

        // ---- Phase B: sliding C window (half2) + weights + half2 accumulation ----
        __half2 Ch[11];
        {
            const unsigned* p = &rc16[trow*RC_STRIDE32 + lx];
            #pragma unroll
            for (int s = 0; s < 11; s++){
                unsigned v0 = p[s*LANES];
                unsigned v1 = p[RC_STRIDE32   + s*LANES];
                unsigned v2 = p[2*RC_STRIDE32 + s*LANES];
                unsigned v3 = p[3*RC_STRIDE32 + s*LANES];
                unsigned v4 = p[4*RC_STRIDE32 + s*LANES];
                __half2 c = __hadd2(*(__half2*)&v0, *(__half2*)&v1);
                c = __hadd2(c, *(__half2*)&v2);
                c = __hadd2(c, *(__half2*)&v3);
                Ch[s] = __hadd2(c, *(__half2*)&v4);
            }
        }
        #pragma unroll
        for (int j = 0; j < RPT; j++){
            if (j == 1){
                const unsigned* pn = &rc16[(trow+5)*RC_STRIDE32 + lx];
                const unsigned* po = &rc16[trow*RC_STRIDE32 + lx];
                #pragma unroll
                for (int s = 0; s < 11; s++){
                    unsigned nv = pn[s*LANES], ov = po[s*LANES];
                    Ch[s] = __hadd2(Ch[s], __hsub2(*(__half2*)&nv, *(__half2*)&ov));
                }
            }
            const int br = trow + j + sy + 5;
            const u64* Brow = &sBp[br*BP_COLS + lx];
            __half2 wh[11];
            __half2 wsum = __float2half2_rn(0.f);
            #pragma unroll
            for (int s = 0; s < 11; s++){
                float2 cf = __half22float2(Ch[s]);
                u64 D2 = fma2_(pk_(cf.x, cf.y), NEG2_2, add2_(Bp2[j], Brow[s]));
                float d0 = fmaxf(lo_(D2), 0.f);
                float d1 = fmaxf(hi_(D2), 0.f);
                float w0 = fex2_a(fsqrt_a(d0) * KEXP);
                float w1 = fex2_a(fsqrt_a(d1) * KEXP);
                __half2 w = __floats2half2_rn(w0, w1);
                wh[s] = w;
                wsum = __hadd2(wsum, w);
            }
            {
                float2 ws = __half22float2(wsum);
                aw2[j] = add2_(aw2[j], pk_(ws.x, ws.y));
            }
            #pragma unroll
            for (int ch = 0; ch < 3; ch++){
                const unsigned* Xrow = &xh[ch*XH_PLANE + br*XH_STRIDE + lx];
                __half2 hacc = __float2half2_rn(0.f);
                #pragma unroll
                for (int s = 0; s < 11; s++){
                    unsigned hx = Xrow[s];
                    hacc = __hfma2(wh[s], *reinterpret_cast<const __half2*>(&hx), hacc);
                }
                float2 av = __half22float2(hacc);
                u64 inc = pk_(av.x, av.y);
                if (ch==0) a02[j] = add2_(a02[j], inc);
                else if (ch==1) a12[j] = add2_(a12[j], inc);
                else a22[j] = add2_(a22[j], inc);
            }
        }
        __syncthreads();   // rc16 reused next sy
    }

    // ---- epilogue: columns (c0+lx, c0+lx+16) ----
    #pragma unroll
    for (int j = 0; j < RPT; j++){
        float rw0 = frcp_a(lo_(aw2[j]));
        float rw1 = frcp_a(hi_(aw2[j]));
        int gr = r0 + trow + j;
        size_t o = (size_t)n*3*HW + ((size_t)gr << 9) + c0 + lx;
        out[o]           = __saturatef(lo_(a02[j])*rw0);
        out[o+16]        = __saturatef(hi_(a02[j])*rw1);
        out[o+HW]        = __saturatef(lo_(a12[j])*rw0);
        out[o+HW+16]     = __saturatef(hi_(a12[j])*rw1);
        out[o+2*HW]      = __saturatef(lo_(a22[j])*rw0);
        out[o+2*HW+16]   = __saturatef(hi_(a22[j])*rw1);
    }
}

extern "C" void kernel_launch(void* const* d_in, const int* in_sizes, int n_in,
                              void* d_out, int out_size){
    const float* x = (const float*)d_in[0];
    float* out = (float*)d_out;
    (void)in_sizes; (void)n_in; (void)out_size;

    cudaFuncSetAttribute(nlm_kernel, cudaFuncAttributeMaxDynamicSharedMemorySize, SMEM_BYTES);

    dim3 grid(WW/TILE_W, HH/TILE_H, NB);   // 16 x 32 x 2
    dim3 block(LANES, TYv);                // 128 threads
    nlm_kernel<<<grid, block, SMEM_BYTES>>>(x, out);
}